// round 15
// baseline (speedup 1.0000x reference)
#include <cuda_runtime.h>
#include <stdint.h>

// out = cos(X @ Win^T + theta) @ Wout^T      X:[262144,64] fp32
// fp16 m16n8k16 single-pass (11-bit mantissa -> rel_err ~4e-4).
// R15: R13 warp-work-stealing, restructured so each 32-token chunk is
// processed as two sequential 16-token m-tiles (peak liveness ~60 regs)
// -> __launch_bounds__(256,3): 24 warps/SM (vs 16), +50% latency hiding.
// Reset-free modular steal counter; .cs on x loads and out stores.

#define NTOK   (32 * 8192)
#define NCHUNK (NTOK / 32)         // 8192 chunks of 32 tokens
#define GRIDSZ 444                 // 3 CTAs/SM persistent
#define NWARPS (GRIDSZ * 8)        // 3552
#define PERIOD (NCHUNK + NWARPS)   // atomics per launch, exactly
#define PITCH4 12                  // uint4 per smem weight row (12%8==4 -> conflict-free)

__device__ unsigned g_ctr;         // zero-init at load; advances PERIOD per launch

__device__ __forceinline__ uint32_t pack_h2(float lo, float hi) {
    uint32_t d;
    asm("cvt.rn.f16x2.f32 %0, %1, %2;" : "=r"(d) : "f"(hi), "f"(lo));
    return d;
}

__device__ __forceinline__ void mma16(float* c, uint32_t a0, uint32_t a1, uint32_t a2, uint32_t a3,
                                      uint32_t b0, uint32_t b1) {
    asm volatile(
        "mma.sync.aligned.m16n8k16.row.col.f32.f16.f16.f32 "
        "{%0,%1,%2,%3}, {%4,%5,%6,%7}, {%8,%9}, {%0,%1,%2,%3};"
        : "+f"(c[0]), "+f"(c[1]), "+f"(c[2]), "+f"(c[3])
        : "r"(a0), "r"(a1), "r"(a2), "r"(a3), "r"(b0), "r"(b1));
}

__device__ __forceinline__ float4 ldcs4(const float* p) {
    float4 v;
    asm volatile("ld.global.cs.v4.f32 {%0,%1,%2,%3}, [%4];"
                 : "=f"(v.x), "=f"(v.y), "=f"(v.z), "=f"(v.w) : "l"(p));
    return v;
}
__device__ __forceinline__ void stcs4(float* p, float a, float b, float c, float d) {
    asm volatile("st.global.cs.v4.f32 [%0], {%1,%2,%3,%4};"
                 :: "l"(p), "f"(a), "f"(b), "f"(c), "f"(d));
}

// Wout row scramble: slot row s holds logical row so thread stores coalesce.
__device__ __forceinline__ int ginv_off(int p) {
    return ((p & 2) >> 1) * 8 + ((p >> 2) & 3) * 2 + (p & 1);
}

__global__ void __launch_bounds__(256, 3)
quantum_fp16_steal3(const float* __restrict__ x,
                    const float* __restrict__ Win,    // [64][64]
                    const float* __restrict__ theta,  // [64]
                    const float* __restrict__ Wout,   // [64][64]
                    float* __restrict__ out)
{
    __shared__ uint32_t sWin[64 * PITCH4 * 4];
    __shared__ uint32_t sWout[64 * PITCH4 * 4];
    __shared__ float    sTh[64];

    const int tid  = threadIdx.x;
    const int lane = tid & 31;
    const int gr   = lane >> 2;
    const int tc   = lane & 3;

    // ---- Weight fill (once per CTA; amortized over ~18 chunks/warp) ----
    for (int idx = tid; idx < 1024; idx += 256) {
        const int r = idx >> 4, c = idx & 15;
        float4 w = *(const float4*)(Win + r * 64 + c * 4);
        const int j = c >> 2, tcw = c & 3;
        uint32_t* quad = &sWin[(r * PITCH4 + (j >> 1) * 4 + tcw) * 4];
        quad[(j & 1) * 2 + 0] = pack_h2(w.x, w.y);
        quad[(j & 1) * 2 + 1] = pack_h2(w.z, w.w);
    }
    for (int idx = tid; idx < 1024; idx += 256) {
        const int r = idx >> 4, c = idx & 15;
        float4 w = *(const float4*)(Wout + r * 64 + c * 4);
        const int s = (r & ~15) | ginv_off(r & 15);
        uint32_t ww0 = pack_h2(w.x, w.y), ww1 = pack_h2(w.z, w.w);
#pragma unroll
        for (int d = 0; d < 2; d++) {
            const int wv = 2 * c + d;
            const int j2 = wv >> 3, v = wv & 7;
            const int tcw  = (v < 4) ? v : v - 4;
            const int elem = (j2 & 1) * 2 + ((v < 4) ? 0 : 1);
            sWout[(s * PITCH4 + (j2 >> 1) * 4 + tcw) * 4 + elem] = d ? ww1 : ww0;
        }
    }
    if (tid < 64) sTh[tid] = theta[tid];
    __syncthreads();

    // ---- Per-warp persistent work-stealing loop ----
    unsigned cur = 0;
    if (lane == 0) cur = atomicAdd(&g_ctr, 1u) % PERIOD;
    cur = __shfl_sync(0xffffffffu, cur, 0);

    while (cur < NCHUNK) {
        const size_t tok0 = (size_t)cur * 32;
        unsigned nxt = 0;

#pragma unroll
        for (int half = 0; half < 2; half++) {
            const size_t tokh = tok0 + half * 16;
            const float* p0 = x + (tokh + gr) * 64 + tc * 4;

            // 8 x LDG.128 for this 16-token m-tile
            float4 v[8];
#pragma unroll
            for (int j = 0; j < 4; j++) {
                v[2 * j + 0] = ldcs4(p0 + j * 16);
                v[2 * j + 1] = ldcs4(p0 + j * 16 + 8 * 64);
            }

            // Steal next chunk under the first half's LDG shadow.
            if (half == 0) {
                if (lane == 0) nxt = atomicAdd(&g_ctr, 1u) % PERIOD;
                nxt = __shfl_sync(0xffffffffu, nxt, 0);
            }

            // Pack A-fragments (v dies)
            uint32_t xa[4][4];
#pragma unroll
            for (int j = 0; j < 4; j++) {
                xa[j][0] = pack_h2(v[2 * j].x,     v[2 * j].y);      // row gr,   k-lo
                xa[j][1] = pack_h2(v[2 * j + 1].x, v[2 * j + 1].y);  // row gr+8, k-lo
                xa[j][2] = pack_h2(v[2 * j].z,     v[2 * j].w);      // row gr,   k-hi
                xa[j][3] = pack_h2(v[2 * j + 1].z, v[2 * j + 1].w);  // row gr+8, k-hi
            }

            // ---- GEMM1 (fp16 k16), 8 independent accumulator chains ----
            float t[8][4];
#pragma unroll
            for (int nt = 0; nt < 8; nt++)
#pragma unroll
                for (int i = 0; i < 4; i++) t[nt][i] = 0.f;

#pragma unroll
            for (int jp = 0; jp < 2; jp++) {
#pragma unroll
                for (int nt = 0; nt < 8; nt++) {
                    const uint4 b = *(const uint4*)&sWin[((8 * nt + gr) * PITCH4 + jp * 4 + tc) * 4];
                    mma16(t[nt], xa[2 * jp][0], xa[2 * jp][1],
                                 xa[2 * jp][2], xa[2 * jp][3], b.x, b.y);
                    mma16(t[nt], xa[2 * jp + 1][0], xa[2 * jp + 1][1],
                                 xa[2 * jp + 1][2], xa[2 * jp + 1][3], b.z, b.w);
                }
            }
            // xa dead.

            // ---- q = cos(t + theta); pack straight into GEMM2 A-frags ----
            uint32_t a2f[4][4];
#pragma unroll
            for (int nt = 0; nt < 8; nt++) {
                const float2 tb = *(const float2*)&sTh[8 * nt + 2 * tc];
                const int j2 = nt >> 1, e = nt & 1;
                float f0 = __cosf(t[nt][0] + tb.x);
                float f1 = __cosf(t[nt][1] + tb.y);
                float f2 = __cosf(t[nt][2] + tb.x);
                float f3 = __cosf(t[nt][3] + tb.y);
                a2f[j2][2 * e + 0] = pack_h2(f0, f1);
                a2f[j2][2 * e + 1] = pack_h2(f2, f3);
            }
            // t dead.

            // ---- GEMM2 per output-tile pair, STG.128 immediately ----
#pragma unroll
            for (int np = 0; np < 4; np++) {
                float acc[2][4];
#pragma unroll
                for (int e = 0; e < 2; e++)
#pragma unroll
                    for (int i = 0; i < 4; i++) acc[e][i] = 0.f;

#pragma unroll
                for (int jp = 0; jp < 2; jp++) {
#pragma unroll
                    for (int e = 0; e < 2; e++) {
                        const int nt2 = 2 * np + e;
                        const uint4 b2 = *(const uint4*)&sWout[((8 * nt2 + gr) * PITCH4 + jp * 4 + tc) * 4];
                        mma16(acc[e], a2f[2 * jp][0], a2f[2 * jp][1],
                                      a2f[2 * jp][2], a2f[2 * jp][3], b2.x, b2.y);
                        mma16(acc[e], a2f[2 * jp + 1][0], a2f[2 * jp + 1][1],
                                      a2f[2 * jp + 1][2], a2f[2 * jp + 1][3], b2.z, b2.w);
                    }
                }

                const int col = np * 16 + tc * 4;
                const size_t r0 = tokh + gr;
                stcs4(out + r0 * 64 + col,
                      acc[0][0], acc[0][1], acc[1][0], acc[1][1]);
                stcs4(out + (r0 + 8) * 64 + col,
                      acc[0][2], acc[0][3], acc[1][2], acc[1][3]);
            }
        }

        cur = nxt;
    }
}

extern "C" void kernel_launch(void* const* d_in, const int* in_sizes, int n_in,
                              void* d_out, int out_size) {
    const float* x     = (const float*)d_in[0];
    const float* W_in  = (const float*)d_in[1];
    const float* theta = (const float*)d_in[2];
    const float* W_out = (const float*)d_in[3];
    float* out = (float*)d_out;

    quantum_fp16_steal3<<<GRIDSZ, 256>>>(x, W_in, theta, W_out, out);
}

// round 16
// speedup vs baseline: 1.7660x; 1.7660x over previous
#include <cuda_runtime.h>
#include <stdint.h>

// out = cos(X @ Win^T + theta) @ Wout^T      X:[262144,64] fp32
// fp16 m16n8k16 single-pass (rel_err ~4e-4). R16: R13 warp-work-stealing
// + cp.async per-warp double-buffered x staging (zero register cost).
// Each thread stages exactly its own 128B (8x16B) per 16-token stage into a
// private 144B-pitch smem region -> no cross-thread visibility needed and
// conflict-free LDS.128 consumption (slot = (lane*9+i) mod 8, distinct/phase).
// Steal = 32-token chunks (atomic count unchanged); pipeline = 16-token stages.

#define NTOK   (32 * 8192)
#define NCHUNK (NTOK / 32)         // 8192 chunks of 32 tokens
#define GRIDSZ 296                 // 2 CTAs/SM persistent
#define NWARPS (GRIDSZ * 8)        // 2368
#define PERIOD (NCHUNK + NWARPS)   // atomics per launch, exactly
#define PITCH4 12                  // uint4 per smem weight row (12%8==4 -> conflict-free)

#define WBUF    4608               // bytes per warp stage buffer (32 lanes x 144B)
#define OFF_WIN  0                 // 64*12*16 = 12288 B
#define OFF_WOUT 12288             // 12288 B
#define OFF_TH   24576             // 256 B
#define OFF_XBUF 24832             // 8 warps x 2 bufs x 4608 = 73728 B
#define SMEM_TOT (OFF_XBUF + 8 * 2 * WBUF)   // 98560 B

__device__ unsigned g_ctr;         // zero-init at load; advances PERIOD per launch

__device__ __forceinline__ uint32_t pack_h2(float lo, float hi) {
    uint32_t d;
    asm("cvt.rn.f16x2.f32 %0, %1, %2;" : "=r"(d) : "f"(hi), "f"(lo));
    return d;
}

__device__ __forceinline__ void mma16(float* c, uint32_t a0, uint32_t a1, uint32_t a2, uint32_t a3,
                                      uint32_t b0, uint32_t b1) {
    asm volatile(
        "mma.sync.aligned.m16n8k16.row.col.f32.f16.f16.f32 "
        "{%0,%1,%2,%3}, {%4,%5,%6,%7}, {%8,%9}, {%0,%1,%2,%3};"
        : "+f"(c[0]), "+f"(c[1]), "+f"(c[2]), "+f"(c[3])
        : "r"(a0), "r"(a1), "r"(a2), "r"(a3), "r"(b0), "r"(b1));
}

__device__ __forceinline__ void stcs4(float* p, float a, float b, float c, float d) {
    asm volatile("st.global.cs.v4.f32 [%0], {%1,%2,%3,%4};"
                 :: "l"(p), "f"(a), "f"(b), "f"(c), "f"(d));
}

// Wout row scramble: slot row s holds logical row so thread stores coalesce.
__device__ __forceinline__ int ginv_off(int p) {
    return ((p & 2) >> 1) * 8 + ((p >> 2) & 3) * 2 + (p & 1);
}

// Stage 16 tokens: thread copies its own 8 x 16B (rows gr, gr+8; col groups j).
__device__ __forceinline__ void prefetch16(const float* __restrict__ x, size_t tok,
                                           int gr, int tc, uint32_t dst) {
    const float* src = x + (tok + gr) * 64 + tc * 4;
#pragma unroll
    for (int j = 0; j < 4; j++) {
        asm volatile("cp.async.cg.shared.global [%0], [%1], 16;"
                     :: "r"(dst + (2 * j) * 16), "l"(src + j * 16));
        asm volatile("cp.async.cg.shared.global [%0], [%1], 16;"
                     :: "r"(dst + (2 * j + 1) * 16), "l"(src + j * 16 + 8 * 64));
    }
    asm volatile("cp.async.commit_group;" ::: "memory");
}

__global__ void __launch_bounds__(256, 2)
quantum_fp16_cpasync(const float* __restrict__ x,
                     const float* __restrict__ Win,    // [64][64]
                     const float* __restrict__ theta,  // [64]
                     const float* __restrict__ Wout,   // [64][64]
                     float* __restrict__ out)
{
    extern __shared__ char smem[];
    uint32_t* sWin  = (uint32_t*)(smem + OFF_WIN);
    uint32_t* sWout = (uint32_t*)(smem + OFF_WOUT);
    float*    sTh   = (float*)(smem + OFF_TH);

    const int tid  = threadIdx.x;
    const int lane = tid & 31;
    const int warp = tid >> 5;
    const int gr   = lane >> 2;
    const int tc   = lane & 3;

    // ---- Weight fill (once per CTA) ----
    for (int idx = tid; idx < 1024; idx += 256) {
        const int r = idx >> 4, c = idx & 15;
        float4 w = *(const float4*)(Win + r * 64 + c * 4);
        const int j = c >> 2, tcw = c & 3;
        uint32_t* quad = &sWin[(r * PITCH4 + (j >> 1) * 4 + tcw) * 4];
        quad[(j & 1) * 2 + 0] = pack_h2(w.x, w.y);
        quad[(j & 1) * 2 + 1] = pack_h2(w.z, w.w);
    }
    for (int idx = tid; idx < 1024; idx += 256) {
        const int r = idx >> 4, c = idx & 15;
        float4 w = *(const float4*)(Wout + r * 64 + c * 4);
        const int s = (r & ~15) | ginv_off(r & 15);
        uint32_t ww0 = pack_h2(w.x, w.y), ww1 = pack_h2(w.z, w.w);
#pragma unroll
        for (int d = 0; d < 2; d++) {
            const int wv = 2 * c + d;
            const int j2 = wv >> 3, v = wv & 7;
            const int tcw  = (v < 4) ? v : v - 4;
            const int elem = (j2 & 1) * 2 + ((v < 4) ? 0 : 1);
            sWout[(s * PITCH4 + (j2 >> 1) * 4 + tcw) * 4 + elem] = d ? ww1 : ww0;
        }
    }
    if (tid < 64) sTh[tid] = theta[tid];
    __syncthreads();

    // Per-warp stage buffers (generic + shared-space addresses)
    char* xb_gen[2];
    uint32_t xb_sh[2];
#pragma unroll
    for (int p = 0; p < 2; p++) {
        xb_gen[p] = smem + OFF_XBUF + (warp * 2 + p) * WBUF + lane * 144;
        xb_sh[p]  = (uint32_t)__cvta_generic_to_shared(xb_gen[p]);
    }

    // ---- Persistent warp loop (reset-free modular steal counter) ----
    unsigned cur = 0;
    if (lane == 0) cur = atomicAdd(&g_ctr, 1u) % PERIOD;
    cur = __shfl_sync(0xffffffffu, cur, 0);

    bool active = cur < NCHUNK;
    int par = 0, half = 0;
    unsigned nxt = NCHUNK;   // sentinel

    if (active) prefetch16(x, (size_t)cur * 32, gr, tc, xb_sh[0]);

    while (active) {
        // Determine + issue the next stage's prefetch (clamped when finishing)
        unsigned pc;  int ph;
        if (half == 0) { pc = cur; ph = 1; }
        else           { pc = (nxt < NCHUNK) ? nxt : cur; ph = (nxt < NCHUNK) ? 0 : 1; }
        prefetch16(x, (size_t)pc * 32 + ph * 16, gr, tc, xb_sh[par ^ 1]);

        // Steal the next chunk during half 0 (hides ATOMG under cp.async)
        if (half == 0) {
            if (lane == 0) nxt = atomicAdd(&g_ctr, 1u) % PERIOD;
            nxt = __shfl_sync(0xffffffffu, nxt, 0);
        }

        // Wait for current stage's data (1 group may remain outstanding)
        asm volatile("cp.async.wait_group 1;" ::: "memory");
        __syncwarp();

        const size_t tokh = (size_t)cur * 32 + half * 16;
        const char* xb = xb_gen[par];

        // Pack A-fragments from staged smem (conflict-free LDS.128)
        uint32_t xa[4][4];
#pragma unroll
        for (int j = 0; j < 4; j++) {
            const float4 v0 = *(const float4*)(xb + (2 * j) * 16);
            const float4 v1 = *(const float4*)(xb + (2 * j + 1) * 16);
            xa[j][0] = pack_h2(v0.x, v0.y);   // row gr,   k-lo
            xa[j][1] = pack_h2(v1.x, v1.y);   // row gr+8, k-lo
            xa[j][2] = pack_h2(v0.z, v0.w);   // row gr,   k-hi
            xa[j][3] = pack_h2(v1.z, v1.w);   // row gr+8, k-hi
        }

        // ---- GEMM1 (fp16 k16), 8 independent accumulator chains ----
        float t[8][4];
#pragma unroll
        for (int nt = 0; nt < 8; nt++)
#pragma unroll
            for (int i = 0; i < 4; i++) t[nt][i] = 0.f;

#pragma unroll
        for (int jp = 0; jp < 2; jp++) {
#pragma unroll
            for (int nt = 0; nt < 8; nt++) {
                const uint4 b = *(const uint4*)&sWin[((8 * nt + gr) * PITCH4 + jp * 4 + tc) * 4];
                mma16(t[nt], xa[2 * jp][0], xa[2 * jp][1],
                             xa[2 * jp][2], xa[2 * jp][3], b.x, b.y);
                mma16(t[nt], xa[2 * jp + 1][0], xa[2 * jp + 1][1],
                             xa[2 * jp + 1][2], xa[2 * jp + 1][3], b.z, b.w);
            }
        }

        // ---- q = cos(t + theta); pack straight into GEMM2 A-frags ----
        uint32_t a2f[4][4];
#pragma unroll
        for (int nt = 0; nt < 8; nt++) {
            const float2 tb = *(const float2*)&sTh[8 * nt + 2 * tc];
            const int j2 = nt >> 1, e = nt & 1;
            float f0 = __cosf(t[nt][0] + tb.x);
            float f1 = __cosf(t[nt][1] + tb.y);
            float f2 = __cosf(t[nt][2] + tb.x);
            float f3 = __cosf(t[nt][3] + tb.y);
            a2f[j2][2 * e + 0] = pack_h2(f0, f1);
            a2f[j2][2 * e + 1] = pack_h2(f2, f3);
        }

        // ---- GEMM2 per output-tile pair, STG.128 immediately ----
#pragma unroll
        for (int np = 0; np < 4; np++) {
            float acc[2][4];
#pragma unroll
            for (int e = 0; e < 2; e++)
#pragma unroll
                for (int i = 0; i < 4; i++) acc[e][i] = 0.f;

#pragma unroll
            for (int jp = 0; jp < 2; jp++) {
#pragma unroll
                for (int e = 0; e < 2; e++) {
                    const int nt2 = 2 * np + e;
                    const uint4 b2 = *(const uint4*)&sWout[((8 * nt2 + gr) * PITCH4 + jp * 4 + tc) * 4];
                    mma16(acc[e], a2f[2 * jp][0], a2f[2 * jp][1],
                                  a2f[2 * jp][2], a2f[2 * jp][3], b2.x, b2.y);
                    mma16(acc[e], a2f[2 * jp + 1][0], a2f[2 * jp + 1][1],
                                  a2f[2 * jp + 1][2], a2f[2 * jp + 1][3], b2.z, b2.w);
                }
            }

            const int col = np * 16 + tc * 4;
            const size_t r0 = tokh + gr;
            stcs4(out + r0 * 64 + col,
                  acc[0][0], acc[0][1], acc[1][0], acc[1][1]);
            stcs4(out + (r0 + 8) * 64 + col,
                  acc[0][2], acc[0][3], acc[1][2], acc[1][3]);
        }

        // Advance stage
        par ^= 1;
        if (half == 0) {
            half = 1;
        } else {
            cur = nxt;
            half = 0;
            active = (cur < NCHUNK);
        }
    }
}

extern "C" void kernel_launch(void* const* d_in, const int* in_sizes, int n_in,
                              void* d_out, int out_size) {
    const float* x     = (const float*)d_in[0];
    const float* W_in  = (const float*)d_in[1];
    const float* theta = (const float*)d_in[2];
    const float* W_out = (const float*)d_in[3];
    float* out = (float*)d_out;

    cudaFuncSetAttribute(quantum_fp16_cpasync,
                         cudaFuncAttributeMaxDynamicSharedMemorySize, SMEM_TOT);
    quantum_fp16_cpasync<<<GRIDSZ, 256, SMEM_TOT>>>(x, W_in, theta, W_out, out);
}

// round 17
// speedup vs baseline: 2.6449x; 1.4977x over previous
#include <cuda_runtime.h>
#include <stdint.h>

// out = cos(X @ Win^T + theta) @ Wout^T      X:[262144,64] fp32
// fp16 m16n8k16 single-pass (rel_err ~4e-4). R17: R13 body verbatim, but the
// single global atomic work-steal counter (theory: one-address L2 atomic
// serialization at ~4cyc/op paced the WHOLE kernel: 8192 grants x ~4.5cyc
// ~= 40k cycles ~= measured duration) is replaced by a static interleaved
// schedule: warp g does chunks g, g+NWARPS, ... Zero atomics, same desync,
// <=1-chunk tail.

#define NTOK   (32 * 8192)
#define NCHUNK (NTOK / 32)         // 8192 chunks of 32 tokens
#define GRIDSZ 296                 // 2 CTAs/SM persistent
#define NWARPS (GRIDSZ * 8)        // 2368
#define PITCH4 12                  // uint4 per smem weight row (12%8==4 -> conflict-free)

__device__ __forceinline__ uint32_t pack_h2(float lo, float hi) {
    uint32_t d;
    asm("cvt.rn.f16x2.f32 %0, %1, %2;" : "=r"(d) : "f"(hi), "f"(lo));
    return d;
}

__device__ __forceinline__ void mma16(float* c, uint32_t a0, uint32_t a1, uint32_t a2, uint32_t a3,
                                      uint32_t b0, uint32_t b1) {
    asm volatile(
        "mma.sync.aligned.m16n8k16.row.col.f32.f16.f16.f32 "
        "{%0,%1,%2,%3}, {%4,%5,%6,%7}, {%8,%9}, {%0,%1,%2,%3};"
        : "+f"(c[0]), "+f"(c[1]), "+f"(c[2]), "+f"(c[3])
        : "r"(a0), "r"(a1), "r"(a2), "r"(a3), "r"(b0), "r"(b1));
}

__device__ __forceinline__ float4 ldcs4(const float* p) {
    float4 v;
    asm volatile("ld.global.cs.v4.f32 {%0,%1,%2,%3}, [%4];"
                 : "=f"(v.x), "=f"(v.y), "=f"(v.z), "=f"(v.w) : "l"(p));
    return v;
}
__device__ __forceinline__ void stcs4(float* p, float a, float b, float c, float d) {
    asm volatile("st.global.cs.v4.f32 [%0], {%1,%2,%3,%4};"
                 :: "l"(p), "f"(a), "f"(b), "f"(c), "f"(d));
}

// Wout row scramble: slot row s holds logical row so thread stores coalesce.
__device__ __forceinline__ int ginv_off(int p) {
    return ((p & 2) >> 1) * 8 + ((p >> 2) & 3) * 2 + (p & 1);
}

__global__ void __launch_bounds__(256, 2)
quantum_fp16_static(const float* __restrict__ x,
                    const float* __restrict__ Win,    // [64][64]
                    const float* __restrict__ theta,  // [64]
                    const float* __restrict__ Wout,   // [64][64]
                    float* __restrict__ out)
{
    __shared__ uint32_t sWin[64 * PITCH4 * 4];
    __shared__ uint32_t sWout[64 * PITCH4 * 4];
    __shared__ float    sTh[64];

    const int tid  = threadIdx.x;
    const int lane = tid & 31;
    const int warp = tid >> 5;
    const int gr   = lane >> 2;
    const int tc   = lane & 3;

    // ---- Weight fill (once per CTA; amortized over ~3.5 chunks/warp) ----
    for (int idx = tid; idx < 1024; idx += 256) {
        const int r = idx >> 4, c = idx & 15;
        float4 w = *(const float4*)(Win + r * 64 + c * 4);
        const int j = c >> 2, tcw = c & 3;
        uint32_t* quad = &sWin[(r * PITCH4 + (j >> 1) * 4 + tcw) * 4];
        quad[(j & 1) * 2 + 0] = pack_h2(w.x, w.y);
        quad[(j & 1) * 2 + 1] = pack_h2(w.z, w.w);
    }
    for (int idx = tid; idx < 1024; idx += 256) {
        const int r = idx >> 4, c = idx & 15;
        float4 w = *(const float4*)(Wout + r * 64 + c * 4);
        const int s = (r & ~15) | ginv_off(r & 15);
        uint32_t ww0 = pack_h2(w.x, w.y), ww1 = pack_h2(w.z, w.w);
#pragma unroll
        for (int d = 0; d < 2; d++) {
            const int wv = 2 * c + d;
            const int j2 = wv >> 3, v = wv & 7;
            const int tcw  = (v < 4) ? v : v - 4;
            const int elem = (j2 & 1) * 2 + ((v < 4) ? 0 : 1);
            sWout[(s * PITCH4 + (j2 >> 1) * 4 + tcw) * 4 + elem] = d ? ww1 : ww0;
        }
    }
    if (tid < 64) sTh[tid] = theta[tid];
    __syncthreads();

    // ---- Static interleaved schedule: warp g -> chunks g, g+NWARPS, ... ----
    const unsigned gwarp = (unsigned)(blockIdx.x * 8 + warp);

    for (unsigned cur = gwarp; cur < NCHUNK; cur += NWARPS) {
        const size_t tok0 = (size_t)cur * 32;
        const float* p0 = x + (tok0 + gr) * 64 + tc * 4;

        // Front-batched x loads (16 x LDG.128, evict-first)
        float4 v[16];
#pragma unroll
        for (int mt = 0; mt < 2; mt++)
#pragma unroll
            for (int j = 0; j < 4; j++) {
                v[mt * 8 + 2 * j + 0] = ldcs4(p0 + (mt * 16) * 64 + j * 16);
                v[mt * 8 + 2 * j + 1] = ldcs4(p0 + (mt * 16 + 8) * 64 + j * 16);
            }

        // Pack A-fragments
        uint32_t xa[2][4][4];
#pragma unroll
        for (int mt = 0; mt < 2; mt++)
#pragma unroll
            for (int j = 0; j < 4; j++) {
                const float4 v0 = v[mt * 8 + 2 * j + 0];
                const float4 v1 = v[mt * 8 + 2 * j + 1];
                xa[mt][j][0] = pack_h2(v0.x, v0.y);   // row gr,   k-lo
                xa[mt][j][1] = pack_h2(v1.x, v1.y);   // row gr+8, k-lo
                xa[mt][j][2] = pack_h2(v0.z, v0.w);   // row gr,   k-hi
                xa[mt][j][3] = pack_h2(v1.z, v1.w);   // row gr+8, k-hi
            }

        // ---- GEMM1 (fp16 k16), 16 independent accumulator chains ----
        float t[2][8][4];
#pragma unroll
        for (int mt = 0; mt < 2; mt++)
#pragma unroll
            for (int nt = 0; nt < 8; nt++)
#pragma unroll
                for (int i = 0; i < 4; i++) t[mt][nt][i] = 0.f;

#pragma unroll
        for (int jp = 0; jp < 2; jp++) {
#pragma unroll
            for (int nt = 0; nt < 8; nt++) {
                const uint4 b = *(const uint4*)&sWin[((8 * nt + gr) * PITCH4 + jp * 4 + tc) * 4];
#pragma unroll
                for (int mt = 0; mt < 2; mt++) {
                    mma16(t[mt][nt], xa[mt][2 * jp][0], xa[mt][2 * jp][1],
                                     xa[mt][2 * jp][2], xa[mt][2 * jp][3], b.x, b.y);
                    mma16(t[mt][nt], xa[mt][2 * jp + 1][0], xa[mt][2 * jp + 1][1],
                                     xa[mt][2 * jp + 1][2], xa[mt][2 * jp + 1][3], b.z, b.w);
                }
            }
        }

        // ---- q = cos(t + theta); pack straight into GEMM2 A-frags ----
        uint32_t a2f[2][4][4];
#pragma unroll
        for (int nt = 0; nt < 8; nt++) {
            const float2 tb = *(const float2*)&sTh[8 * nt + 2 * tc];
            const int j2 = nt >> 1, e = nt & 1;
#pragma unroll
            for (int mt = 0; mt < 2; mt++) {
                float f0 = __cosf(t[mt][nt][0] + tb.x);
                float f1 = __cosf(t[mt][nt][1] + tb.y);
                float f2 = __cosf(t[mt][nt][2] + tb.x);
                float f3 = __cosf(t[mt][nt][3] + tb.y);
                a2f[mt][j2][2 * e + 0] = pack_h2(f0, f1);
                a2f[mt][j2][2 * e + 1] = pack_h2(f2, f3);
            }
        }

        // ---- GEMM2 per output-tile pair, STG.128 immediately ----
#pragma unroll
        for (int np = 0; np < 4; np++) {
            float acc[2][2][4];
#pragma unroll
            for (int mt = 0; mt < 2; mt++)
#pragma unroll
                for (int e = 0; e < 2; e++)
#pragma unroll
                    for (int i = 0; i < 4; i++) acc[mt][e][i] = 0.f;

#pragma unroll
            for (int jp = 0; jp < 2; jp++) {
#pragma unroll
                for (int e = 0; e < 2; e++) {
                    const int nt2 = 2 * np + e;
                    const uint4 b2 = *(const uint4*)&sWout[((8 * nt2 + gr) * PITCH4 + jp * 4 + tc) * 4];
#pragma unroll
                    for (int mt = 0; mt < 2; mt++) {
                        mma16(acc[mt][e], a2f[mt][2 * jp][0], a2f[mt][2 * jp][1],
                                          a2f[mt][2 * jp][2], a2f[mt][2 * jp][3], b2.x, b2.y);
                        mma16(acc[mt][e], a2f[mt][2 * jp + 1][0], a2f[mt][2 * jp + 1][1],
                                          a2f[mt][2 * jp + 1][2], a2f[mt][2 * jp + 1][3], b2.z, b2.w);
                    }
                }
            }

            const int col = np * 16 + tc * 4;
#pragma unroll
            for (int mt = 0; mt < 2; mt++) {
                const size_t r0 = tok0 + mt * 16 + gr;
                stcs4(out + r0 * 64 + col,
                      acc[mt][0][0], acc[mt][0][1], acc[mt][1][0], acc[mt][1][1]);
                stcs4(out + (r0 + 8) * 64 + col,
                      acc[mt][0][2], acc[mt][0][3], acc[mt][1][2], acc[mt][1][3]);
            }
        }
    }
}

extern "C" void kernel_launch(void* const* d_in, const int* in_sizes, int n_in,
                              void* d_out, int out_size) {
    const float* x     = (const float*)d_in[0];
    const float* W_in  = (const float*)d_in[1];
    const float* theta = (const float*)d_in[2];
    const float* W_out = (const float*)d_in[3];
    float* out = (float*)d_out;

    quantum_fp16_static<<<GRIDSZ, 256>>>(x, W_in, theta, W_out, out);
}